// round 11
// baseline (speedup 1.0000x reference)
#include <cuda_runtime.h>
#include <cuda_bf16.h>
#include <cstdint>

// VoxelPooler: bin points into quarter-row segments (b,z,x,y/50), then a
// fused rowpool: counting-sort entries by exact y inside the CTA, and each
// warp gathers its 8-channel slice (2x LDG.128 per entry), accumulates in
// registers (packed f32x2 adds), and writes coalesced STG.32 directly.
// NO smem accumulation tile: no zero phase, no tile LDS/STS, no readout LDS.
// All warps process all entries (disjoint channel slices) -> no imbalance.
//
// geometry [B,N,D,H,W,3] f32, features [B,N,D,H,W,64] f32
// output   [B, Z*C, X, Y] f32, Z=8 C=64 X=200 Y=200

constexpr int GX = 200;
constexpr int GY = 200;
constexpr int GZ = 8;
constexpr int CH = 64;
constexpr int XY = GX * GY;
constexpr int NB = 4;
constexpr int PPB   = 6 * 41 * 16 * 44;    // 173184
constexpr int PTOT  = NB * PPB;            // 692736
constexpr int SEGY  = 50;                  // y-span per segment
constexpr int NSEG  = NB * GZ * GX * 4;    // 25600
constexpr int CAP   = 64;                  // slots/seg; occupancy ~Poisson(18)

__device__ int      d_count[NSEG];                  // zero-init; re-zeroed by rowpool
__device__ unsigned d_plist[(size_t)NSEG * CAP];    // (p<<8)|y_local  (6.55 MB)

__global__ void __launch_bounds__(256) vp_bin_fill(
    const float* __restrict__ geo,
    const float* __restrict__ vsize,
    const float* __restrict__ vorig)
{
    int t = blockIdx.x * blockDim.x + threadIdx.x;

    float ox = __ldg(&vorig[0]), oy = __ldg(&vorig[1]), oz = __ldg(&vorig[2]);
    float sx = __ldg(&vsize[0]), sy = __ldg(&vsize[1]), sz = __ldg(&vsize[2]);

    #pragma unroll
    for (int k = 0; k < 2; ++k) {               // 2 points/thread: 2 indep chains
        int p = t + k * (PTOT / 2);
        if (p >= PTOT) continue;

        const float* g = geo + (size_t)p * 3;
        float px = g[0], py = g[1], pz = g[2];

        // fp32 semantics matching jnp: sub(rn), div(rn), floorf, int cast
        int ix = (int)floorf(__fdiv_rn(px - ox, sx));
        int iy = (int)floorf(__fdiv_rn(py - oy, sy));
        int iz = (int)floorf(__fdiv_rn(pz - oz, sz));

        if ((unsigned)ix >= (unsigned)GX ||
            (unsigned)iy >= (unsigned)GY ||
            (unsigned)iz >= (unsigned)GZ) continue;   // ref scatters zeros: no-op

        int b  = p / PPB;
        int yq = iy / SEGY;
        int yl = iy - yq * SEGY;                      // 0..49
        int seg = ((((b * GZ + iz) * GX) + ix) << 2) + yq;
        int pos = atomicAdd(&d_count[seg], 1);
        if (pos < CAP)
            d_plist[(size_t)seg * CAP + pos] = ((unsigned)p << 8) | (unsigned)yl;
    }
}

// One CTA per quarter-row segment; 8 warps; warp w owns channels 8w..8w+7.
__global__ void __launch_bounds__(256) vp_rowpool(
    const float* __restrict__ feat,
    float* __restrict__ out)
{
    __shared__ int      start[SEGY + 1];   // exclusive bin offsets
    __shared__ int      cur[SEGY];         // counters, then cursors
    __shared__ unsigned sorted[CAP];       // point ids grouped by y

    int r = blockIdx.x;
    int tid = threadIdx.x, warp = tid >> 5, lane = tid & 31;

    if (tid < SEGY) cur[tid] = 0;
    int n = d_count[r];                    // broadcast load
    if (n > CAP) n = CAP;
    unsigned e0 = 0;
    bool h = tid < n;                      // n <= 64
    if (h) e0 = d_plist[(size_t)r * CAP + tid];
    __syncthreads();

    if (h) atomicAdd(&cur[e0 & 255u], 1);
    if (tid == 0) d_count[r] = 0;          // reset for next graph replay
    __syncthreads();

    // warp 0: exclusive scan of 50 bins -> start[0..50] and cursors
    if (warp == 0) {
        int v0 = cur[lane];                                  // bins 0..31
        int v1 = (lane + 32 < SEGY) ? cur[lane + 32] : 0;    // bins 32..49
        int s0 = v0;
        #pragma unroll
        for (int d = 1; d < 32; d <<= 1) { int x2 = __shfl_up_sync(~0u, s0, d); if (lane >= d) s0 += x2; }
        int tot0 = __shfl_sync(~0u, s0, 31);
        int s1 = v1;
        #pragma unroll
        for (int d = 1; d < 32; d <<= 1) { int x2 = __shfl_up_sync(~0u, s1, d); if (lane >= d) s1 += x2; }
        s1 += tot0;
        if (lane == 0) start[0] = 0;
        start[lane + 1] = s0;                                // start[1..32]
        if (lane + 32 < SEGY) start[lane + 33] = s1;         // start[33..50]
        cur[lane] = s0 - v0;                                 // exclusive cursor
        if (lane + 32 < SEGY) cur[lane + 32] = s1 - v1;
    }
    __syncthreads();

    if (h) sorted[atomicAdd(&cur[e0 & 255u], 1)] = e0 >> 8;  // point id
    __syncthreads();

    // fused gather + accumulate + store
    int row = r >> 2, q = r & 3;
    int b  = row / (GZ * GX);
    int zx = row % (GZ * GX);
    int z = zx / GX, x = zx % GX;
    float* ob = out + ((size_t)(b * GZ + z) * CH) * XY
                    + (size_t)x * GY + q * SEGY;
    const float* fw = feat + (warp << 3);        // this warp's 8-channel slice

    #pragma unroll
    for (int j = 0; j < 2; ++j) {
        int y = lane + (j << 5);
        if (y < SEGY) {                          // j=0: all lanes; j=1: lanes<18
            int s  = start[y];
            int e2 = start[y + 1];
            unsigned long long A0 = 0, A1 = 0, A2 = 0, A3 = 0;   // 8 ch packed f32x2
            for (int e = s; e < e2; ++e) {
                unsigned p = sorted[e];
                const ulonglong2* f =
                    (const ulonglong2*)(fw + (size_t)p * CH);    // 16B aligned
                ulonglong2 u = f[0], v = f[1];                    // 2x LDG.128
                asm("add.rn.f32x2 %0, %0, %1;" : "+l"(A0) : "l"(u.x));
                asm("add.rn.f32x2 %0, %0, %1;" : "+l"(A1) : "l"(u.y));
                asm("add.rn.f32x2 %0, %0, %1;" : "+l"(A2) : "l"(v.x));
                asm("add.rn.f32x2 %0, %0, %1;" : "+l"(A3) : "l"(v.y));
            }
            // 8 coalesced STG.32 (consecutive lanes -> consecutive y)
            float* o2 = ob + (size_t)(warp << 3) * XY + y;
            uint2 w0 = *(uint2*)&A0, w1 = *(uint2*)&A1;
            uint2 w2 = *(uint2*)&A2, w3 = *(uint2*)&A3;
            o2[0]              = __uint_as_float(w0.x);
            o2[(size_t)1 * XY] = __uint_as_float(w0.y);
            o2[(size_t)2 * XY] = __uint_as_float(w1.x);
            o2[(size_t)3 * XY] = __uint_as_float(w1.y);
            o2[(size_t)4 * XY] = __uint_as_float(w2.x);
            o2[(size_t)5 * XY] = __uint_as_float(w2.y);
            o2[(size_t)6 * XY] = __uint_as_float(w3.x);
            o2[(size_t)7 * XY] = __uint_as_float(w3.y);
        }
    }
}

extern "C" void kernel_launch(void* const* d_in, const int* in_sizes, int n_in,
                              void* d_out, int out_size)
{
    const float* geo   = (const float*)d_in[0];
    const float* feat  = (const float*)d_in[1];
    const float* vsize = (const float*)d_in[2];
    const float* vorig = (const float*)d_in[3];
    float* out = (float*)d_out;

    vp_bin_fill<<<(PTOT / 2 + 255) / 256, 256>>>(geo, vsize, vorig);
    vp_rowpool<<<NSEG, 256>>>(feat, out);
}

// round 13
// speedup vs baseline: 1.7685x; 1.7685x over previous
#include <cuda_runtime.h>
#include <cuda_bf16.h>
#include <cstdint>

// VoxelPooler: bin points into per-(half-row, y%8-class) sub-lists in ONE
// pass, then a lean rowpool: warp w consumes its own pre-grouped class list
// (no in-CTA sort, 2 barriers total), coalesced feature loads (one point per
// warp-op, lanes = channels), race-free smem accumulate, structured readout.
//
// Tile: Y-MAJOR, stride 65: acc[yl*65 + c]   (half-row: 100 y, 26 KB, 8 CTA/SM)
//   accumulate: lane l, fixed y -> bank (y+l)%32    conflict-free
//   readout:    fixed c, y=32j+l -> bank (l+c)%32   conflict-free, STG coalesced
//
// geometry [B,N,D,H,W,3] f32, features [B,N,D,H,W,64] f32
// output   [B, Z*C, X, Y] f32, Z=8 C=64 X=200 Y=200

constexpr int GX = 200;
constexpr int GY = 200;
constexpr int GZ = 8;
constexpr int CH = 64;
constexpr int XY = GX * GY;
constexpr int NB = 4;
constexpr int PPB   = 6 * 41 * 16 * 44;    // 173184
constexpr int PTOT  = NB * PPB;            // 692736
constexpr int HY    = GY / 2;              // 100
constexpr int NSEG  = NB * GZ * GX * 2;    // 12800 half-row segments
constexpr int NCLS  = NSEG * 8;            // 102400 class lists
constexpr int PADC  = CH + 1;              // 65
constexpr int CAPC  = 32;                  // slots/class; occupancy ~Poisson(4.5)

__device__ int      d_count[NCLS];                  // zero-init; re-zeroed by rowpool
__device__ unsigned d_plist[(size_t)NCLS * CAPC];   // (p<<8)|y_local  (13.1 MB)

__global__ void __launch_bounds__(256) vp_bin_fill(
    const float* __restrict__ geo,
    const float* __restrict__ vsize,
    const float* __restrict__ vorig)
{
    int t = blockIdx.x * blockDim.x + threadIdx.x;

    float ox = __ldg(&vorig[0]), oy = __ldg(&vorig[1]), oz = __ldg(&vorig[2]);
    float sx = __ldg(&vsize[0]), sy = __ldg(&vsize[1]), sz = __ldg(&vsize[2]);

    #pragma unroll
    for (int k = 0; k < 2; ++k) {              // 2 points/thread, indep chains
        int p = t + k * (PTOT / 2);
        if (p >= PTOT) continue;

        const float* g = geo + (size_t)p * 3;
        float px = g[0], py = g[1], pz = g[2];

        // fp32 semantics matching jnp: sub(rn), div(rn), floorf, int cast
        int ix = (int)floorf(__fdiv_rn(px - ox, sx));
        int iy = (int)floorf(__fdiv_rn(py - oy, sy));
        int iz = (int)floorf(__fdiv_rn(pz - oz, sz));

        if ((unsigned)ix >= (unsigned)GX ||
            (unsigned)iy >= (unsigned)GY ||
            (unsigned)iz >= (unsigned)GZ) continue;   // ref scatters zeros: no-op

        int b   = p / PPB;
        int yh  = iy >= HY;
        int yl  = iy - yh * HY;                       // 0..99
        int cl  = ((((b * GZ + iz) * GX + ix) << 1) + yh) * 8 + (yl & 7);
        int pos = atomicAdd(&d_count[cl], 1);
        if (pos < CAPC)
            d_plist[(size_t)cl * CAPC + pos] = ((unsigned)p << 8) | (unsigned)yl;
    }
}

// One CTA per half-row segment; warp w consumes class list w.
__global__ void __launch_bounds__(256) vp_rowpool(
    const float* __restrict__ feat,
    float* __restrict__ out)
{
    __shared__ float acc[HY * PADC];      // 100*65*4 = 26000 B, y-major

    int r = blockIdx.x;
    int tid = threadIdx.x, warp = tid >> 5, lane = tid & 31;
    int cl = (r << 3) + warp;

    // issue list-count + entry loads early (consumed after the barrier)
    int nw = d_count[cl];                 // per-warp broadcast load
    if (nw > CAPC) nw = CAPC;
    unsigned e = 0;
    if (lane < nw) e = d_plist[(size_t)cl * CAPC + lane];   // coalesced
    if (lane == 0) d_count[cl] = 0;       // reset for next graph replay

    // zero tile (float4)
    float4* accv = reinterpret_cast<float4*>(acc);
    #pragma unroll
    for (int i = tid; i < (HY * PADC) / 4; i += 256)
        accv[i] = make_float4(0.f, 0.f, 0.f, 0.f);
    __syncthreads();

    // accumulate: entries live in lane registers, broadcast via shfl.
    // one point per warp-op -> feature LDG coalesced (2 x 128B lines).
    int j = 0;
    for (; j + 1 < nw; j += 2) {
        unsigned ea = __shfl_sync(~0u, e, j);
        unsigned eb = __shfl_sync(~0u, e, j + 1);
        const float* fa = feat + (size_t)(ea >> 8) * CH;
        const float* fb = feat + (size_t)(eb >> 8) * CH;
        float a0 = fa[lane], a1 = fa[lane + 32];
        float b0 = fb[lane], b1 = fb[lane + 32];
        int ya = (int)(ea & 255u) * PADC;
        int yb = (int)(eb & 255u) * PADC;
        acc[ya + lane]      += a0;        // bank (y+l)%32: conflict-free
        acc[ya + lane + 32] += a1;
        acc[yb + lane]      += b0;
        acc[yb + lane + 32] += b1;
    }
    if (j < nw) {
        unsigned ea = __shfl_sync(~0u, e, j);
        const float* fa = feat + (size_t)(ea >> 8) * CH;
        float a0 = fa[lane], a1 = fa[lane + 32];
        int ya = (int)(ea & 255u) * PADC;
        acc[ya + lane]      += a0;
        acc[ya + lane + 32] += a1;
    }
    __syncthreads();

    // readout: warp w owns channels 8w..8w+7; lane strides y by 32.
    // LDS bank (l+c)%32 conflict-free; STG.32 coalesced; no divisions.
    int row = r >> 1;
    int ybase = (r & 1) * HY;
    int b  = row / (GZ * GX);
    int zx = row % (GZ * GX);
    int z = zx / GX, x = zx % GX;
    float* ob = out + ((size_t)(b * GZ + z) * CH) * XY + (size_t)x * GY + ybase;

    #pragma unroll
    for (int ci = 0; ci < 8; ++ci) {
        int c = (warp << 3) + ci;
        const float* arow = acc + c;
        float* orow = ob + (size_t)c * XY;
        #pragma unroll
        for (int jj = 0; jj < 3; ++jj) {               // yl = lane + 32jj
            int yl = lane + (jj << 5);
            orow[yl] = arow[(size_t)yl * PADC];
        }
        if (lane < 4) {                                // yl = 96..99
            int yl = 96 + lane;
            orow[yl] = arow[(size_t)yl * PADC];
        }
    }
}

extern "C" void kernel_launch(void* const* d_in, const int* in_sizes, int n_in,
                              void* d_out, int out_size)
{
    const float* geo   = (const float*)d_in[0];
    const float* feat  = (const float*)d_in[1];
    const float* vsize = (const float*)d_in[2];
    const float* vorig = (const float*)d_in[3];
    float* out = (float*)d_out;

    vp_bin_fill<<<(PTOT / 2 + 255) / 256, 256>>>(geo, vsize, vorig);
    vp_rowpool<<<NSEG, 256>>>(feat, out);
}